// round 10
// baseline (speedup 1.0000x reference)
#include <cuda_runtime.h>
#include <math.h>
#include <stdint.h>

#define Nn 64
#define T  512
#define Dd 512
#define Hh 512
#define G4 2048   // 4*H
#define NB 128    // persistent blocks
#define BPG 32    // blocks per batch group

// ---------------- scratch (static device arrays) ----------------
__device__ __align__(128) float g_xW[(size_t)Nn * T * G4];   // [t][n][4H]
__device__ __align__(128) float g_hd[2][Hh * Nn * 2];        // dup hidden: [k][n][2]
__device__ int g_gcnt[4];   // per-group arrival counters
__device__ int g_flag[4];   // per-group completed-step flags

// Packed dual-lane fp32 FMA (Blackwell FFMA2; only reachable via PTX f32x2)
__device__ __forceinline__ void fma2(unsigned long long& d,
                                     unsigned long long a,
                                     unsigned long long b) {
    asm("fma.rn.f32x2 %0, %1, %2, %0;" : "+l"(d) : "l"(a), "l"(b));
}
__device__ __forceinline__ unsigned long long dup2(float v) {
    unsigned long long d;
    asm("mov.b64 %0, {%1, %1};" : "=l"(d) : "f"(v));
    return d;
}
__device__ __forceinline__ float2 u2f2(unsigned long long v) {
    float2 r;
    asm("mov.b64 {%0,%1}, %2;" : "=f"(r.x), "=f"(r.y) : "l"(v));
    return r;
}
static __device__ __forceinline__ uint32_t s2u(const void* p) {
    return (uint32_t)__cvta_generic_to_shared(p);
}
static __device__ __forceinline__ void cpasync16(uint32_t dst, const void* src) {
    asm volatile("cp.async.cg.shared.global [%0], [%1], 16;" :: "r"(dst), "l"(src));
}

// ---------------------------------------------------------------------------
// GEMM 1: xW = x @ Wx + b, relaid [t][n][4H].
// 128x128 tile, BK=8, 256 threads, 8x8 microtile.
// f32x2: A-pairs natural from smem (m contiguous), B dup'd in registers.
// ---------------------------------------------------------------------------
__global__ __launch_bounds__(256) void gemm_xw(const float* __restrict__ x,
                                               const float* __restrict__ Wx,
                                               const float* __restrict__ b) {
    __shared__ float As[2][8][128];   // [k][m]
    __shared__ float Bs[2][8][128];   // [k][n]

    const int tid = threadIdx.x;
    const int tx = tid & 15;
    const int ty = tid >> 4;
    const int m0 = blockIdx.y * 128;
    const int n0 = blockIdx.x * 128;

    const int a_m = tid >> 1;
    const int a_k = (tid & 1) * 4;
    const int b_c = (tid & 31) * 4;
    const int b_k = tid >> 5;

    unsigned long long acc[4][8];   // [m-pair][col]
#pragma unroll
    for (int i = 0; i < 4; i++)
#pragma unroll
        for (int j = 0; j < 8; j++) acc[i][j] = 0ULL;

    float4 pa = *(const float4*)&x[(size_t)(m0 + a_m) * Dd + a_k];
    float4 pb = *(const float4*)&Wx[(size_t)b_k * G4 + n0 + b_c];
    As[0][a_k + 0][a_m] = pa.x;
    As[0][a_k + 1][a_m] = pa.y;
    As[0][a_k + 2][a_m] = pa.z;
    As[0][a_k + 3][a_m] = pa.w;
    *(float4*)&Bs[0][b_k][b_c] = pb;
    __syncthreads();

    const int NSTAGE = Dd / 8;
    for (int s = 0; s < NSTAGE; s++) {
        const int cur = s & 1;
        if (s + 1 < NSTAGE) {
            const int k0 = (s + 1) * 8;
            pa = *(const float4*)&x[(size_t)(m0 + a_m) * Dd + k0 + a_k];
            pb = *(const float4*)&Wx[(size_t)(k0 + b_k) * G4 + n0 + b_c];
        }
#pragma unroll
        for (int k = 0; k < 8; k++) {
            ulonglong2 a01 = *(ulonglong2*)&As[cur][k][ty * 8];
            ulonglong2 a23 = *(ulonglong2*)&As[cur][k][ty * 8 + 4];
            float4 b0 = *(float4*)&Bs[cur][k][tx * 8];
            float4 b1 = *(float4*)&Bs[cur][k][tx * 8 + 4];
            unsigned long long ap[4] = {a01.x, a01.y, a23.x, a23.y};
            unsigned long long bd[8] = {dup2(b0.x), dup2(b0.y), dup2(b0.z),
                                        dup2(b0.w), dup2(b1.x), dup2(b1.y),
                                        dup2(b1.z), dup2(b1.w)};
#pragma unroll
            for (int i = 0; i < 4; i++)
#pragma unroll
                for (int j = 0; j < 8; j++) fma2(acc[i][j], ap[i], bd[j]);
        }
        if (s + 1 < NSTAGE) {
            const int nxt = cur ^ 1;
            As[nxt][a_k + 0][a_m] = pa.x;
            As[nxt][a_k + 1][a_m] = pa.y;
            As[nxt][a_k + 2][a_m] = pa.z;
            As[nxt][a_k + 3][a_m] = pa.w;
            *(float4*)&Bs[nxt][b_k][b_c] = pb;
            __syncthreads();
        }
    }

    float4 bb0 = *(const float4*)&b[n0 + tx * 8];
    float4 bb1 = *(const float4*)&b[n0 + tx * 8 + 4];
    const float bias[8] = {bb0.x, bb0.y, bb0.z, bb0.w, bb1.x, bb1.y, bb1.z, bb1.w};
#pragma unroll
    for (int i = 0; i < 4; i++) {
        float2 c[8];
#pragma unroll
        for (int j = 0; j < 8; j++) c[j] = u2f2(acc[i][j]);
#pragma unroll
        for (int l = 0; l < 2; l++) {
            int m = m0 + ty * 8 + i * 2 + l;
            int tt = m & (T - 1);
            int nn = m >> 9;
            size_t row = ((size_t)tt * Nn + nn) * G4 + n0 + tx * 8;
            float v[8];
#pragma unroll
            for (int j = 0; j < 8; j++) v[j] = (l ? c[j].y : c[j].x) + bias[j];
            *(float4*)&g_xW[row]     = make_float4(v[0], v[1], v[2], v[3]);
            *(float4*)&g_xW[row + 4] = make_float4(v[4], v[5], v[6], v[7]);
        }
    }
}

// ---------------------------------------------------------------------------
// Init: g_hd[0][k][n][2] = {h0[n][k], h0[n][k]}; reset counters/flags.
// ---------------------------------------------------------------------------
__global__ void lstm_init(const float* __restrict__ h0) {
    int i = blockIdx.x * blockDim.x + threadIdx.x;
    if (i < Nn * Hh) {
        int n = i & 63;
        int k = i >> 6;
        float v = h0[n * Hh + k];
        *(float2*)&g_hd[0][(k * Nn + n) * 2] = make_float2(v, v);
    }
    if (i < 4) { g_gcnt[i] = 0; g_flag[i] = 0; }
}

// ---------------------------------------------------------------------------
// Persistent scan, batch-partitioned, 512 threads/block (4 warps/SMSP for
// latency hiding). 4 groups of 32 blocks; block (ng, hg): batch [ng*16,+16),
// hidden [hg*16,+16). D[16n][64c], k-split 8 inside the block.
// smem: W fp32 [512][64] 128KB | h-dup [512][32] 64KB | sacc [8][16][68]
// (pad 68 floats = 272B, 16B-aligned rows for float4 LDS — pad 66 traps).
// ---------------------------------------------------------------------------
__global__ __launch_bounds__(512) void lstm_scan(const float* __restrict__ Wh,
                                                 float* __restrict__ out) {
    extern __shared__ float sm[];
    float* ws   = sm;                    // [512][64]
    float* hs   = sm + 512 * 64;         // [512][32]
    float* sacc = hs + 512 * 32;         // [8][16][68]

    const int tid = threadIdx.x;
    const int hb  = blockIdx.x;
    const int ng  = hb >> 5;            // batch group
    const int hg  = hb & 31;            // hidden group
    const int ks  = tid >> 6;           // k sub-slice 0..7
    const int r   = tid & 63;
    const int mq  = r & 7;              // n-pair index
    const int cq  = r >> 3;             // c-octet index
    const int n_e = tid & 15;           // epilogue: local batch
    const int u_e = tid >> 4;           // epilogue: local hidden unit (tid<256)

    // resident W slice: ws[k][u*4+g] = Wh[k][g*512 + hg*16 + u]
    for (int idx = tid; idx < 512 * 64; idx += 512) {
        int k = idx >> 6;
        int c = idx & 63;
        int u = c >> 2;
        int g = c & 3;
        ws[idx] = Wh[(size_t)k * G4 + g * Hh + hg * 16 + u];
    }

    const uint32_t h_smem = s2u(hs);
    float c_reg = 0.f;

    for (int t = 0; t < T; t++) {
        const int cur = t & 1;
        const float* hsrc = g_hd[cur];
        float*       hdst = g_hd[cur ^ 1];

        // prefetch this step's xW gate slice (epilogue threads only)
        float xw0, xw1, xw2, xw3;
        const int gn = ng * 16 + n_e;
        if (tid < 256) {
            const float* xwp = g_xW + ((size_t)t * Nn + gn) * G4 + hg * 16 + u_e;
            xw0 = xwp[0 * Hh];
            xw1 = xwp[1 * Hh];
            xw2 = xwp[2 * Hh];
            xw3 = xwp[3 * Hh];
        }

        // --- stage dup-h slice: 4 chunks of 16KB, one commit group each ---
#pragma unroll
        for (int c = 0; c < 4; c++) {
#pragma unroll
            for (int q = 0; q < 2; q++) {
                int id  = q * 512 + tid;          // 0..1023
                int k_l = id >> 3;                // 0..127
                int prt = id & 7;                 // 16B part of 128B row
                uint32_t dst = h_smem + (uint32_t)((c * 128 + k_l) * 128 + prt * 16);
                const char* src = (const char*)hsrc +
                                  (size_t)(c * 128 + k_l) * 512 + ng * 128 + prt * 16;
                cpasync16(dst, src);
            }
            asm volatile("cp.async.commit_group;");
        }

        // --- 4 overlapped GEMM phases; ks covers 16 k of each chunk ---
        unsigned long long a00 = 0, a01 = 0, a02 = 0, a03 = 0;
        unsigned long long a10 = 0, a11 = 0, a12 = 0, a13 = 0;

#define GEMM_PHASE(C, WG)                                                     \
        {                                                                     \
            asm volatile("cp.async.wait_group %0;" :: "n"(WG));               \
            __syncthreads();                                                  \
            const float* hbp = hs + ((C) * 128 + ks * 16) * 32 + mq * 4;      \
            const float* wbp = ws + ((C) * 128 + ks * 16) * 64 + cq * 8;      \
            _Pragma("unroll 8")                                               \
            for (int k = 0; k < 16; k++) {                                    \
                ulonglong2 hd = *(const ulonglong2*)(hbp + k * 32);           \
                ulonglong2 w0 = *(const ulonglong2*)(wbp + k * 64);           \
                ulonglong2 w1 = *(const ulonglong2*)(wbp + k * 64 + 4);       \
                fma2(a00, hd.x, w0.x); fma2(a01, hd.x, w0.y);                 \
                fma2(a02, hd.x, w1.x); fma2(a03, hd.x, w1.y);                 \
                fma2(a10, hd.y, w0.x); fma2(a11, hd.y, w0.y);                 \
                fma2(a12, hd.y, w1.x); fma2(a13, hd.y, w1.y);                 \
            }                                                                 \
        }
        GEMM_PHASE(0, 3)
        GEMM_PHASE(1, 2)
        GEMM_PHASE(2, 1)
        GEMM_PHASE(3, 0)
#undef GEMM_PHASE

        // --- partials -> sacc[ks][n][c] (pad 68) ---
        {
            float* p0 = &sacc[(ks * 16 + mq * 2 + 0) * 68 + cq * 8];
            float* p1 = &sacc[(ks * 16 + mq * 2 + 1) * 68 + cq * 8];
            ((unsigned long long*)p0)[0] = a00;
            ((unsigned long long*)p0)[1] = a01;
            ((unsigned long long*)p0)[2] = a02;
            ((unsigned long long*)p0)[3] = a03;
            ((unsigned long long*)p1)[0] = a10;
            ((unsigned long long*)p1)[1] = a11;
            ((unsigned long long*)p1)[2] = a12;
            ((unsigned long long*)p1)[3] = a13;
        }
        __syncthreads();

        // --- epilogue: threads 0..255 handle (n_e, u_e) ---
        if (tid < 256) {
            float ai = 0.f, af = 0.f, ao = 0.f, ag = 0.f;
#pragma unroll
            for (int s = 0; s < 8; s++) {
                float4 v = *(float4*)&sacc[(s * 16 + n_e) * 68 + u_e * 4];
                ai += v.x; af += v.y; ao += v.z; ag += v.w;
            }
            ai += xw0; af += xw1; ao += xw2; ag += xw3;

            float iv = 1.f / (1.f + expf(-ai));
            float fv = 1.f / (1.f + expf(-af));
            float ov = 1.f / (1.f + expf(-ao));
            float gv = tanhf(ag);

            c_reg = fv * c_reg + iv * gv;
            float hn = ov * tanhf(c_reg);

            const int gk = hg * 16 + u_e;
            *(float2*)&hdst[(gk * Nn + gn) * 2] = make_float2(hn, hn);
            out[((size_t)gn * T + t) * Hh + gk] = hn;
        }
        __syncthreads();

        // --- per-group barrier (32 blocks) ---
        if (tid == 0) {
            __threadfence();
            int v = atomicAdd(&g_gcnt[ng], 1);
            if (v == BPG - 1) {
                g_gcnt[ng] = 0;
                __threadfence();
                *(volatile int*)&g_flag[ng] = t + 1;
            } else {
                while (*(volatile int*)&g_flag[ng] < t + 1) { }
            }
            __threadfence();
        }
        __syncthreads();
    }
}

// ---------------------------------------------------------------------------
// Launch
// ---------------------------------------------------------------------------
extern "C" void kernel_launch(void* const* d_in, const int* in_sizes, int n_in,
                              void* d_out, int out_size) {
    const float* x  = (const float*)d_in[0];
    const float* h0 = (const float*)d_in[1];
    const float* Wx = (const float*)d_in[2];
    const float* Wh = (const float*)d_in[3];
    const float* b  = (const float*)d_in[4];
    float* out = (float*)d_out;

    const int smem = (512 * 64 + 512 * 32 + 8 * 16 * 68) * sizeof(float);
    cudaFuncSetAttribute(lstm_scan, cudaFuncAttributeMaxDynamicSharedMemorySize, smem);

    dim3 g1(G4 / 128, (Nn * T) / 128);
    gemm_xw<<<g1, 256>>>(x, Wx, b);
    lstm_init<<<(Nn * Hh + 255) / 256, 256>>>(h0);
    lstm_scan<<<NB, 512, smem>>>(Wh, out);
}

// round 11
// speedup vs baseline: 1.1277x; 1.1277x over previous
#include <cuda_runtime.h>
#include <math.h>
#include <stdint.h>

#define Nn 64
#define T  512
#define Dd 512
#define Hh 512
#define G4 2048   // 4*H
#define NB 128    // persistent blocks
#define BPG 32    // blocks per batch group

// ---------------- scratch (static device arrays) ----------------
__device__ __align__(128) float g_xW[(size_t)Nn * T * G4];   // [t][n][4H]
__device__ __align__(128) float g_h[2][Hh * Nn];             // hidden, [k][n]
__device__ int g_gcnt[4];   // per-group arrival counters
__device__ int g_flag[4];   // per-group completed-step flags

// Packed dual-lane fp32 FMA (Blackwell FFMA2; only reachable via PTX f32x2)
__device__ __forceinline__ void fma2(unsigned long long& d,
                                     unsigned long long a,
                                     unsigned long long b) {
    asm("fma.rn.f32x2 %0, %1, %2, %0;" : "+l"(d) : "l"(a), "l"(b));
}
__device__ __forceinline__ unsigned long long dup2(float v) {
    unsigned long long d;
    asm("mov.b64 %0, {%1, %1};" : "=l"(d) : "f"(v));
    return d;
}
__device__ __forceinline__ float2 u2f2(unsigned long long v) {
    float2 r;
    asm("mov.b64 {%0,%1}, %2;" : "=f"(r.x), "=f"(r.y) : "l"(v));
    return r;
}
static __device__ __forceinline__ uint32_t s2u(const void* p) {
    return (uint32_t)__cvta_generic_to_shared(p);
}
static __device__ __forceinline__ void cpasync16(uint32_t dst, const void* src) {
    asm volatile("cp.async.cg.shared.global [%0], [%1], 16;" :: "r"(dst), "l"(src));
}

// ---------------------------------------------------------------------------
// GEMM 1: xW = x @ Wx + b, relaid [t][n][4H].
// 128x128 tile, BK=8, 256 threads, 8x8 microtile, f32x2 with reg-dup B.
// Warp footprint remapped to 4(m-tiles) x 8(n-tiles): unique smem bytes per
// warp per k = 384B (was 576B with the 2x16 footprint) — kernel is L1-bound.
// ---------------------------------------------------------------------------
__global__ __launch_bounds__(256) void gemm_xw(const float* __restrict__ x,
                                               const float* __restrict__ Wx,
                                               const float* __restrict__ b) {
    __shared__ float As[2][8][128];   // [k][m]
    __shared__ float Bs[2][8][128];   // [k][n]

    const int tid  = threadIdx.x;
    const int lane = tid & 31;
    const int wrp  = tid >> 5;
    const int mt = (wrp >> 1) * 4 + (lane >> 3);   // m-tile 0..15
    const int nt = (wrp & 1) * 8 + (lane & 7);     // n-tile 0..15
    const int m0 = blockIdx.y * 128;
    const int n0 = blockIdx.x * 128;

    const int a_m = tid >> 1;
    const int a_k = (tid & 1) * 4;
    const int b_c = (tid & 31) * 4;
    const int b_k = tid >> 5;

    unsigned long long acc[4][8];   // [m-pair][col]
#pragma unroll
    for (int i = 0; i < 4; i++)
#pragma unroll
        for (int j = 0; j < 8; j++) acc[i][j] = 0ULL;

    float4 pa = *(const float4*)&x[(size_t)(m0 + a_m) * Dd + a_k];
    float4 pb = *(const float4*)&Wx[(size_t)b_k * G4 + n0 + b_c];
    As[0][a_k + 0][a_m] = pa.x;
    As[0][a_k + 1][a_m] = pa.y;
    As[0][a_k + 2][a_m] = pa.z;
    As[0][a_k + 3][a_m] = pa.w;
    *(float4*)&Bs[0][b_k][b_c] = pb;
    __syncthreads();

    const int NSTAGE = Dd / 8;
    for (int s = 0; s < NSTAGE; s++) {
        const int cur = s & 1;
        if (s + 1 < NSTAGE) {
            const int k0 = (s + 1) * 8;
            pa = *(const float4*)&x[(size_t)(m0 + a_m) * Dd + k0 + a_k];
            pb = *(const float4*)&Wx[(size_t)(k0 + b_k) * G4 + n0 + b_c];
        }
#pragma unroll
        for (int k = 0; k < 8; k++) {
            ulonglong2 a01 = *(ulonglong2*)&As[cur][k][mt * 8];
            ulonglong2 a23 = *(ulonglong2*)&As[cur][k][mt * 8 + 4];
            float4 b0 = *(float4*)&Bs[cur][k][nt * 8];
            float4 b1 = *(float4*)&Bs[cur][k][nt * 8 + 4];
            unsigned long long ap[4] = {a01.x, a01.y, a23.x, a23.y};
            unsigned long long bd[8] = {dup2(b0.x), dup2(b0.y), dup2(b0.z),
                                        dup2(b0.w), dup2(b1.x), dup2(b1.y),
                                        dup2(b1.z), dup2(b1.w)};
#pragma unroll
            for (int i = 0; i < 4; i++)
#pragma unroll
                for (int j = 0; j < 8; j++) fma2(acc[i][j], ap[i], bd[j]);
        }
        if (s + 1 < NSTAGE) {
            const int nxt = cur ^ 1;
            As[nxt][a_k + 0][a_m] = pa.x;
            As[nxt][a_k + 1][a_m] = pa.y;
            As[nxt][a_k + 2][a_m] = pa.z;
            As[nxt][a_k + 3][a_m] = pa.w;
            *(float4*)&Bs[nxt][b_k][b_c] = pb;
            __syncthreads();
        }
    }

    float4 bb0 = *(const float4*)&b[n0 + nt * 8];
    float4 bb1 = *(const float4*)&b[n0 + nt * 8 + 4];
    const float bias[8] = {bb0.x, bb0.y, bb0.z, bb0.w, bb1.x, bb1.y, bb1.z, bb1.w};
#pragma unroll
    for (int i = 0; i < 4; i++) {
        float2 c[8];
#pragma unroll
        for (int j = 0; j < 8; j++) c[j] = u2f2(acc[i][j]);
#pragma unroll
        for (int l = 0; l < 2; l++) {
            int m = m0 + mt * 8 + i * 2 + l;
            int tt = m & (T - 1);
            int nn = m >> 9;
            size_t row = ((size_t)tt * Nn + nn) * G4 + n0 + nt * 8;
            float v[8];
#pragma unroll
            for (int j = 0; j < 8; j++) v[j] = (l ? c[j].y : c[j].x) + bias[j];
            *(float4*)&g_xW[row]     = make_float4(v[0], v[1], v[2], v[3]);
            *(float4*)&g_xW[row + 4] = make_float4(v[4], v[5], v[6], v[7]);
        }
    }
}

// ---------------------------------------------------------------------------
// Init: g_h[0][k][n] = h0[n][k]; reset counters/flags.
// ---------------------------------------------------------------------------
__global__ void lstm_init(const float* __restrict__ h0) {
    int i = blockIdx.x * blockDim.x + threadIdx.x;
    if (i < Nn * Hh) {
        int n = i & 63;
        int k = i >> 6;
        g_h[0][k * Nn + n] = h0[n * Hh + k];
    }
    if (i < 4) { g_gcnt[i] = 0; g_flag[i] = 0; }
}

// ---------------------------------------------------------------------------
// Persistent scan (r8 structure, 256 threads; h stored plain [k][n],
// pair-duplication done in registers — staging halves to 32KB/block/step).
// 4 groups of 32 blocks; block (ng, hg): batch [ng*16,+16), hidden [hg*16,+16).
// D[16n][64c] (c = u*4+g), k-split 4, per-thread tile 2n x 8c.
// smem: W fp32 [512][64] 128KB | h [512][16] 32KB | sacc [4][16][68] 17KB.
// ---------------------------------------------------------------------------
__global__ __launch_bounds__(256) void lstm_scan(const float* __restrict__ Wh,
                                                 float* __restrict__ out) {
    extern __shared__ float sm[];
    float* ws   = sm;                    // [512][64]
    float* hs   = sm + 512 * 64;         // [512][16]
    float* sacc = hs + 512 * 16;         // [4][16][68]

    const int tid = threadIdx.x;
    const int hb  = blockIdx.x;
    const int ng  = hb >> 5;            // batch group
    const int hg  = hb & 31;            // hidden group
    const int ks  = tid >> 6;           // k sub-slice 0..3
    const int r   = tid & 63;
    const int mq  = r & 7;              // n-pair index (n = 2mq, 2mq+1)
    const int cq  = r >> 3;             // c-octet index (c = cq*8..+8)
    const int n_e = tid & 15;           // epilogue: local batch
    const int u_e = tid >> 4;           // epilogue: local hidden unit

    // resident W slice: ws[k][u*4+g] = Wh[k][g*512 + hg*16 + u]
    for (int idx = tid; idx < 512 * 64; idx += 256) {
        int k = idx >> 6;
        int c = idx & 63;
        int u = c >> 2;
        int g = c & 3;
        ws[idx] = Wh[(size_t)k * G4 + g * Hh + hg * 16 + u];
    }

    const uint32_t h_smem = s2u(hs);
    float c_reg = 0.f;

    for (int t = 0; t < T; t++) {
        const int cur = t & 1;
        const float* hsrc = g_h[cur];            // [k][64n]
        float*       hdst = g_h[cur ^ 1];

        // prefetch this step's xW gate slice
        const int gn = ng * 16 + n_e;
        const float* xwp = g_xW + ((size_t)t * Nn + gn) * G4 + hg * 16 + u_e;
        float xw0 = xwp[0 * Hh];
        float xw1 = xwp[1 * Hh];
        float xw2 = xwp[2 * Hh];
        float xw3 = xwp[3 * Hh];

        // --- stage h slice [k][16n]: 4 chunks of 8KB (128 k x 64B) ---
#pragma unroll
        for (int c = 0; c < 4; c++) {
#pragma unroll
            for (int q = 0; q < 2; q++) {
                int id  = q * 256 + tid;          // 0..511
                int k_l = id >> 2;                // 0..127
                int prt = id & 3;                 // 16B part of 64B row
                uint32_t dst = h_smem + (uint32_t)((c * 128 + k_l) * 64 + prt * 16);
                const char* src = (const char*)hsrc +
                                  (size_t)(c * 128 + k_l) * 256 + ng * 64 + prt * 16;
                cpasync16(dst, src);
            }
            asm volatile("cp.async.commit_group;");
        }

        // --- 4 overlapped GEMM phases; ks covers 32 k of each chunk ---
        unsigned long long a00 = 0, a01 = 0, a02 = 0, a03 = 0;
        unsigned long long a10 = 0, a11 = 0, a12 = 0, a13 = 0;

#define GEMM_PHASE(C, WG)                                                     \
        {                                                                     \
            asm volatile("cp.async.wait_group %0;" :: "n"(WG));               \
            __syncthreads();                                                  \
            const float* hbp = hs + ((C) * 128 + ks * 32) * 16 + mq * 2;      \
            const float* wbp = ws + ((C) * 128 + ks * 32) * 64 + cq * 8;      \
            _Pragma("unroll 8")                                               \
            for (int k = 0; k < 32; k++) {                                    \
                float2 hv = *(const float2*)(hbp + k * 16);                   \
                unsigned long long h0d = dup2(hv.x);                          \
                unsigned long long h1d = dup2(hv.y);                          \
                ulonglong2 w0 = *(const ulonglong2*)(wbp + k * 64);           \
                ulonglong2 w1 = *(const ulonglong2*)(wbp + k * 64 + 4);       \
                fma2(a00, h0d, w0.x); fma2(a01, h0d, w0.y);                   \
                fma2(a02, h0d, w1.x); fma2(a03, h0d, w1.y);                   \
                fma2(a10, h1d, w0.x); fma2(a11, h1d, w0.y);                   \
                fma2(a12, h1d, w1.x); fma2(a13, h1d, w1.y);                   \
            }                                                                 \
        }
        GEMM_PHASE(0, 3)
        GEMM_PHASE(1, 2)
        GEMM_PHASE(2, 1)
        GEMM_PHASE(3, 0)
#undef GEMM_PHASE

        // --- partials -> sacc[ks][n][c] (pad 68, 16B-aligned rows) ---
        {
            float* p0 = &sacc[(ks * 16 + mq * 2 + 0) * 68 + cq * 8];
            float* p1 = &sacc[(ks * 16 + mq * 2 + 1) * 68 + cq * 8];
            ((unsigned long long*)p0)[0] = a00;
            ((unsigned long long*)p0)[1] = a01;
            ((unsigned long long*)p0)[2] = a02;
            ((unsigned long long*)p0)[3] = a03;
            ((unsigned long long*)p1)[0] = a10;
            ((unsigned long long*)p1)[1] = a11;
            ((unsigned long long*)p1)[2] = a12;
            ((unsigned long long*)p1)[3] = a13;
        }
        __syncthreads();

        // --- epilogue: thread handles (n_e, u_e); gates at c = u_e*4 + g ---
        {
            float4 s0 = *(float4*)&sacc[(0 * 16 + n_e) * 68 + u_e * 4];
            float4 s1 = *(float4*)&sacc[(1 * 16 + n_e) * 68 + u_e * 4];
            float4 s2 = *(float4*)&sacc[(2 * 16 + n_e) * 68 + u_e * 4];
            float4 s3 = *(float4*)&sacc[(3 * 16 + n_e) * 68 + u_e * 4];
            float ai = s0.x + s1.x + s2.x + s3.x + xw0;
            float af = s0.y + s1.y + s2.y + s3.y + xw1;
            float ao = s0.z + s1.z + s2.z + s3.z + xw2;
            float ag = s0.w + s1.w + s2.w + s3.w + xw3;

            float iv = 1.f / (1.f + expf(-ai));
            float fv = 1.f / (1.f + expf(-af));
            float ov = 1.f / (1.f + expf(-ao));
            float gv = tanhf(ag);

            c_reg = fv * c_reg + iv * gv;
            float hn = ov * tanhf(c_reg);

            const int gk = hg * 16 + u_e;
            hdst[gk * Nn + gn] = hn;                         // [k][n], coalesced
            out[((size_t)gn * T + t) * Hh + gk] = hn;
        }
        __syncthreads();

        // --- per-group barrier (32 blocks) ---
        if (tid == 0) {
            __threadfence();
            int v = atomicAdd(&g_gcnt[ng], 1);
            if (v == BPG - 1) {
                g_gcnt[ng] = 0;
                __threadfence();
                *(volatile int*)&g_flag[ng] = t + 1;
            } else {
                while (*(volatile int*)&g_flag[ng] < t + 1) { }
            }
            __threadfence();
        }
        __syncthreads();
    }
}

// ---------------------------------------------------------------------------
// Launch
// ---------------------------------------------------------------------------
extern "C" void kernel_launch(void* const* d_in, const int* in_sizes, int n_in,
                              void* d_out, int out_size) {
    const float* x  = (const float*)d_in[0];
    const float* h0 = (const float*)d_in[1];
    const float* Wx = (const float*)d_in[2];
    const float* Wh = (const float*)d_in[3];
    const float* b  = (const float*)d_in[4];
    float* out = (float*)d_out;

    const int smem = (512 * 64 + 512 * 16 + 4 * 16 * 68) * sizeof(float);
    cudaFuncSetAttribute(lstm_scan, cudaFuncAttributeMaxDynamicSharedMemorySize, smem);

    dim3 g1(G4 / 128, (Nn * T) / 128);
    gemm_xw<<<g1, 256>>>(x, Wx, b);
    lstm_init<<<(Nn * Hh + 255) / 256, 256>>>(h0);
    lstm_scan<<<NB, 256, smem>>>(Wh, out);
}

// round 13
// speedup vs baseline: 1.3943x; 1.2365x over previous
#include <cuda_runtime.h>
#include <cuda_bf16.h>
#include <math.h>
#include <stdint.h>

#define Nn 64
#define T  512
#define Dd 512
#define Hh 512
#define G4 2048   // 4*H
#define NB 128    // persistent blocks
#define BPG 32    // blocks per batch group

// ---------------- scratch (static device arrays) ----------------
__device__ __align__(128) float g_xW[(size_t)Nn * T * G4];          // [t][n][4H]
__device__ __align__(128) __nv_bfloat16 g_hh[2][Nn * Hh];           // h hi plane [n][k]
__device__ __align__(128) __nv_bfloat16 g_hl[2][Nn * Hh];           // h lo plane [n][k]
__device__ int g_gcnt[4];
__device__ int g_flag[4];

// ---------------- helpers ----------------
__device__ __forceinline__ void fma2(unsigned long long& d,
                                     unsigned long long a,
                                     unsigned long long b) {
    asm("fma.rn.f32x2 %0, %1, %2, %0;" : "+l"(d) : "l"(a), "l"(b));
}
__device__ __forceinline__ unsigned long long dup2(float v) {
    unsigned long long d;
    asm("mov.b64 %0, {%1, %1};" : "=l"(d) : "f"(v));
    return d;
}
__device__ __forceinline__ float2 u2f2(unsigned long long v) {
    float2 r;
    asm("mov.b64 {%0,%1}, %2;" : "=f"(r.x), "=f"(r.y) : "l"(v));
    return r;
}
static __device__ __forceinline__ uint32_t s2u(const void* p) {
    return (uint32_t)__cvta_generic_to_shared(p);
}
static __device__ __forceinline__ void cpasync16(uint32_t dst, const void* src) {
    asm volatile("cp.async.cg.shared.global [%0], [%1], 16;" :: "r"(dst), "l"(src));
}
static __device__ __forceinline__ void ldsm4(uint32_t* r, uint32_t addr) {
    asm volatile("ldmatrix.sync.aligned.m8n8.x4.shared.b16 {%0,%1,%2,%3}, [%4];"
                 : "=r"(r[0]), "=r"(r[1]), "=r"(r[2]), "=r"(r[3]) : "r"(addr));
}
static __device__ __forceinline__ void mma16816(float* d, const uint32_t* a,
                                                uint32_t b0, uint32_t b1) {
    asm volatile("mma.sync.aligned.m16n8k16.row.col.f32.bf16.bf16.f32 "
                 "{%0,%1,%2,%3},{%4,%5,%6,%7},{%8,%9},{%0,%1,%2,%3};"
                 : "+f"(d[0]), "+f"(d[1]), "+f"(d[2]), "+f"(d[3])
                 : "r"(a[0]), "r"(a[1]), "r"(a[2]), "r"(a[3]), "r"(b0), "r"(b1));
}

// smem byte layout (pitch 1040 B = 520 halves, ldsm conflict-free: 1040/4 mod 32 = 4)
#define OFF_WHI  0                         // [64c][520] bf16  = 66560
#define OFF_WLO  66560                     // [64c][520] bf16
#define OFF_HH   133120                    // [16n][520] bf16  = 16640
#define OFF_HL   149760                    // [16n][520] bf16
#define OFF_SACC 166400                    // [4][64][20] fp32 = 20480
#define SMEM_BYTES (OFF_SACC + 4 * 64 * 20 * 4)

// ---------------------------------------------------------------------------
// GEMM 1 (r11 version, best measured): xW = x @ Wx + b, relaid [t][n][4H].
// ---------------------------------------------------------------------------
__global__ __launch_bounds__(256) void gemm_xw(const float* __restrict__ x,
                                               const float* __restrict__ Wx,
                                               const float* __restrict__ b) {
    __shared__ float As[2][8][128];
    __shared__ float Bs[2][8][128];

    const int tid  = threadIdx.x;
    const int lane = tid & 31;
    const int wrp  = tid >> 5;
    const int mt = (wrp >> 1) * 4 + (lane >> 3);
    const int nt = (wrp & 1) * 8 + (lane & 7);
    const int m0 = blockIdx.y * 128;
    const int n0 = blockIdx.x * 128;

    const int a_m = tid >> 1;
    const int a_k = (tid & 1) * 4;
    const int b_c = (tid & 31) * 4;
    const int b_k = tid >> 5;

    unsigned long long acc[4][8];
#pragma unroll
    for (int i = 0; i < 4; i++)
#pragma unroll
        for (int j = 0; j < 8; j++) acc[i][j] = 0ULL;

    float4 pa = *(const float4*)&x[(size_t)(m0 + a_m) * Dd + a_k];
    float4 pb = *(const float4*)&Wx[(size_t)b_k * G4 + n0 + b_c];
    As[0][a_k + 0][a_m] = pa.x;
    As[0][a_k + 1][a_m] = pa.y;
    As[0][a_k + 2][a_m] = pa.z;
    As[0][a_k + 3][a_m] = pa.w;
    *(float4*)&Bs[0][b_k][b_c] = pb;
    __syncthreads();

    const int NSTAGE = Dd / 8;
    for (int s = 0; s < NSTAGE; s++) {
        const int cur = s & 1;
        if (s + 1 < NSTAGE) {
            const int k0 = (s + 1) * 8;
            pa = *(const float4*)&x[(size_t)(m0 + a_m) * Dd + k0 + a_k];
            pb = *(const float4*)&Wx[(size_t)(k0 + b_k) * G4 + n0 + b_c];
        }
#pragma unroll
        for (int k = 0; k < 8; k++) {
            ulonglong2 a01 = *(ulonglong2*)&As[cur][k][mt * 8];
            ulonglong2 a23 = *(ulonglong2*)&As[cur][k][mt * 8 + 4];
            float4 b0 = *(float4*)&Bs[cur][k][nt * 8];
            float4 b1 = *(float4*)&Bs[cur][k][nt * 8 + 4];
            unsigned long long ap[4] = {a01.x, a01.y, a23.x, a23.y};
            unsigned long long bd[8] = {dup2(b0.x), dup2(b0.y), dup2(b0.z),
                                        dup2(b0.w), dup2(b1.x), dup2(b1.y),
                                        dup2(b1.z), dup2(b1.w)};
#pragma unroll
            for (int i = 0; i < 4; i++)
#pragma unroll
                for (int j = 0; j < 8; j++) fma2(acc[i][j], ap[i], bd[j]);
        }
        if (s + 1 < NSTAGE) {
            const int nxt = cur ^ 1;
            As[nxt][a_k + 0][a_m] = pa.x;
            As[nxt][a_k + 1][a_m] = pa.y;
            As[nxt][a_k + 2][a_m] = pa.z;
            As[nxt][a_k + 3][a_m] = pa.w;
            *(float4*)&Bs[nxt][b_k][b_c] = pb;
            __syncthreads();
        }
    }

    float4 bb0 = *(const float4*)&b[n0 + nt * 8];
    float4 bb1 = *(const float4*)&b[n0 + nt * 8 + 4];
    const float bias[8] = {bb0.x, bb0.y, bb0.z, bb0.w, bb1.x, bb1.y, bb1.z, bb1.w};
#pragma unroll
    for (int i = 0; i < 4; i++) {
        float2 c[8];
#pragma unroll
        for (int j = 0; j < 8; j++) c[j] = u2f2(acc[i][j]);
#pragma unroll
        for (int l = 0; l < 2; l++) {
            int m = m0 + mt * 8 + i * 2 + l;
            int tt = m & (T - 1);
            int nn = m >> 9;
            size_t row = ((size_t)tt * Nn + nn) * G4 + n0 + nt * 8;
            float v[8];
#pragma unroll
            for (int j = 0; j < 8; j++) v[j] = (l ? c[j].y : c[j].x) + bias[j];
            *(float4*)&g_xW[row]     = make_float4(v[0], v[1], v[2], v[3]);
            *(float4*)&g_xW[row + 4] = make_float4(v[4], v[5], v[6], v[7]);
        }
    }
}

// ---------------------------------------------------------------------------
// Init: h0 -> bf16 hi/lo planes [n][k]; reset counters/flags.
// ---------------------------------------------------------------------------
__global__ void lstm_init(const float* __restrict__ h0) {
    int i = blockIdx.x * blockDim.x + threadIdx.x;
    if (i < Nn * Hh) {
        float v = h0[i];                    // [n][k] layout matches
        __nv_bfloat16 hi = __float2bfloat16(v);
        __nv_bfloat16 lo = __float2bfloat16(v - __bfloat162float(hi));
        g_hh[0][i] = hi;
        g_hl[0][i] = lo;
    }
    if (i < 4) { g_gcnt[i] = 0; g_flag[i] = 0; }
}

// ---------------------------------------------------------------------------
// Persistent HMMA scan (mma.sync m16n8k16 bf16 — the r5-proven fragment
// scheme on the r11 partition). 4 groups x 32 blocks; block (ng,hg):
// batch [ng*16,+16), cols c = u*4+g for hidden [hg*16,+16).
// A = W planes [64c][512k] resident; B = h planes [16n][512k], 32KB/step
// staged in 4 overlapped cp.async chunks. 3-term split, fp32 accum.
// Warp wid: mw = wid&1 (c half), kw = wid>>1 (k quarter); per staged chunk
// each warp does its 2 mma-k-chunks -> staging overlaps compute.
// ---------------------------------------------------------------------------
__global__ __launch_bounds__(256) void lstm_scan(const float* __restrict__ Wh,
                                                 float* __restrict__ out) {
    extern __shared__ char smem[];
    __nv_bfloat16* whi = (__nv_bfloat16*)(smem + OFF_WHI);
    __nv_bfloat16* wlo = (__nv_bfloat16*)(smem + OFF_WLO);
    float* sacc = (float*)(smem + OFF_SACC);   // [4][64][20]

    const int tid  = threadIdx.x;
    const int lane = tid & 31;
    const int wid  = tid >> 5;
    const int hb   = blockIdx.x;
    const int ng   = hb >> 5;
    const int hg   = hb & 31;
    const int mw   = wid & 1;          // c half: rows [mw*32, +32)
    const int kw   = wid >> 1;         // k quarter
    const int n_e  = tid & 15;         // epilogue: local batch
    const int u_e  = tid >> 4;         // epilogue: local hidden unit

    // --- resident W planes, [c][k] pitch 520 halves; c = u*4 + g ---
    for (int idx = tid; idx < 64 * 512; idx += 256) {
        int c = idx & 63;
        int k = idx >> 6;
        int u = c >> 2;
        int g = c & 3;
        float w = Wh[(size_t)k * G4 + g * Hh + hg * 16 + u];
        __nv_bfloat16 hi = __float2bfloat16(w);
        whi[c * 520 + k] = hi;
        wlo[c * 520 + k] = __float2bfloat16(w - __bfloat162float(hi));
    }

    // ldmatrix lane addressing (r5-proven)
    const int tile = lane >> 3;
    const int tr   = lane & 7;
    const uint32_t a_row16 = (tile & 1) * 8 + tr;       // row within m16
    const uint32_t a_koff  = (tile >> 1) * 16;          // bytes
    const uint32_t b_c     = (tile >> 1) * 8 + tr;      // n within 16
    const uint32_t b_koff  = (tile & 1) * 16;           // bytes
    // A bases for this warp's two m-tiles (c rows mw*32 and mw*32+16)
    const uint32_t aHi0 = s2u(whi) + (mw * 32 + a_row16) * 1040 + a_koff;
    const uint32_t aHi1 = aHi0 + 16 * 1040;
    const uint32_t aLo0 = s2u(wlo) + (mw * 32 + a_row16) * 1040 + a_koff;
    const uint32_t aLo1 = aLo0 + 16 * 1040;
    const uint32_t bHH  = s2u(smem + OFF_HH) + b_c * 1040 + b_koff;
    const uint32_t bHL  = s2u(smem + OFF_HL) + b_c * 1040 + b_koff;

    float c_reg = 0.f;

    for (int t = 0; t < T; t++) {
        const int cur = t & 1;
        const __nv_bfloat16* ghh = g_hh[cur];
        const __nv_bfloat16* ghl = g_hl[cur];

        // prefetch this step's xW gate slice
        const int gn = ng * 16 + n_e;
        const int gk = hg * 16 + u_e;
        const float* xwp = g_xW + ((size_t)t * Nn + gn) * G4 + hg * 16 + u_e;
        float xw0 = xwp[0 * Hh];
        float xw1 = xwp[1 * Hh];
        float xw2 = xwp[2 * Hh];
        float xw3 = xwp[3 * Hh];

        // --- stage h planes: 4 chunks; chunk c = k16 units [c*16, c*16+16) ---
#pragma unroll
        for (int c = 0; c < 4; c++) {
#pragma unroll
            for (int it = 0; it < 2; it++) {
                int id = it * 256 + tid;          // 0..511
                int p  = id >> 8;                 // plane
                int n  = (id >> 4) & 15;
                int q  = c * 16 + (id & 15);      // k16 unit (16B)
                uint32_t dst = s2u(smem + (p ? OFF_HL : OFF_HH)) +
                               (uint32_t)n * 1040u + (uint32_t)q * 16u;
                const char* src = (const char*)(p ? ghl : ghh) +
                                  (size_t)(ng * 16 + n) * 1024 + (size_t)q * 16;
                cpasync16(dst, src);
            }
            asm volatile("cp.async.commit_group;");
        }

        // --- 4 overlapped MMA phases; per phase this warp does 2 k-chunks ---
        float d00[4] = {0, 0, 0, 0}, d01[4] = {0, 0, 0, 0};
        float d10[4] = {0, 0, 0, 0}, d11[4] = {0, 0, 0, 0};

#define MMA_PHASE(C, WG)                                                      \
        {                                                                     \
            asm volatile("cp.async.wait_group %0;" :: "n"(WG));               \
            __syncthreads();                                                  \
            _Pragma("unroll")                                                 \
            for (int kc2 = 0; kc2 < 2; kc2++) {                               \
                const uint32_t off = (uint32_t)(((C) * 8 + kw * 2 + kc2) * 32); \
                uint32_t ah0[4], ah1[4], al0[4], al1[4], bh[4], bl[4];        \
                ldsm4(ah0, aHi0 + off);                                       \
                ldsm4(ah1, aHi1 + off);                                       \
                ldsm4(bh,  bHH  + off);                                       \
                ldsm4(bl,  bHL  + off);                                       \
                ldsm4(al0, aLo0 + off);                                       \
                ldsm4(al1, aLo1 + off);                                       \
                mma16816(d00, ah0, bh[0], bh[1]);                             \
                mma16816(d01, ah0, bh[2], bh[3]);                             \
                mma16816(d10, ah1, bh[0], bh[1]);                             \
                mma16816(d11, ah1, bh[2], bh[3]);                             \
                mma16816(d00, ah0, bl[0], bl[1]);                             \
                mma16816(d01, ah0, bl[2], bl[3]);                             \
                mma16816(d10, ah1, bl[0], bl[1]);                             \
                mma16816(d11, ah1, bl[2], bl[3]);                             \
                mma16816(d00, al0, bh[0], bh[1]);                             \
                mma16816(d01, al0, bh[2], bh[3]);                             \
                mma16816(d10, al1, bh[0], bh[1]);                             \
                mma16816(d11, al1, bh[2], bh[3]);                             \
            }                                                                 \
        }
        MMA_PHASE(0, 3)
        MMA_PHASE(1, 2)
        MMA_PHASE(2, 1)
        MMA_PHASE(3, 0)
#undef MMA_PHASE

        // --- D frags -> sacc[kw][c][n] (pitch 20) ---
        {
            const int crow = mw * 32 + (lane >> 2);
            const int ncol = (lane & 3) * 2;
            float* sa = sacc + kw * 64 * 20;
            *(float2*)&sa[(crow)      * 20 + ncol]     = make_float2(d00[0], d00[1]);
            *(float2*)&sa[(crow + 8)  * 20 + ncol]     = make_float2(d00[2], d00[3]);
            *(float2*)&sa[(crow)      * 20 + ncol + 8] = make_float2(d01[0], d01[1]);
            *(float2*)&sa[(crow + 8)  * 20 + ncol + 8] = make_float2(d01[2], d01[3]);
            *(float2*)&sa[(crow + 16) * 20 + ncol]     = make_float2(d10[0], d10[1]);
            *(float2*)&sa[(crow + 24) * 20 + ncol]     = make_float2(d10[2], d10[3]);
            *(float2*)&sa[(crow + 16) * 20 + ncol + 8] = make_float2(d11[0], d11[1]);
            *(float2*)&sa[(crow + 24) * 20 + ncol + 8] = make_float2(d11[2], d11[3]);
        }
        __syncthreads();

        // --- epilogue: thread (n_e, u_e); gates at c = u_e*4 + g ---
        {
            float ag[4];
#pragma unroll
            for (int g = 0; g < 4; g++) {
                int c = u_e * 4 + g;
                ag[g] = sacc[(0 * 64 + c) * 20 + n_e]
                      + sacc[(1 * 64 + c) * 20 + n_e]
                      + sacc[(2 * 64 + c) * 20 + n_e]
                      + sacc[(3 * 64 + c) * 20 + n_e];
            }
            ag[0] += xw0; ag[1] += xw1; ag[2] += xw2; ag[3] += xw3;

            float iv = 1.f / (1.f + expf(-ag[0]));
            float fv = 1.f / (1.f + expf(-ag[1]));
            float ov = 1.f / (1.f + expf(-ag[2]));
            float gv = tanhf(ag[3]);

            c_reg = fv * c_reg + iv * gv;
            float hn = ov * tanhf(c_reg);

            __nv_bfloat16 hi = __float2bfloat16(hn);
            g_hh[cur ^ 1][gn * Hh + gk] = hi;
            g_hl[cur ^ 1][gn * Hh + gk] =
                __float2bfloat16(hn - __bfloat162float(hi));
            out[((size_t)gn * T + t) * Hh + gk] = hn;
        }
        __syncthreads();

        // --- per-group barrier (32 blocks) ---
        if (tid == 0) {
            __threadfence();
            int v = atomicAdd(&g_gcnt[ng], 1);
            if (v == BPG - 1) {
                g_gcnt[ng] = 0;
                __threadfence();
                *(volatile int*)&g_flag[ng] = t + 1;
            } else {
                while (*(volatile int*)&g_flag[ng] < t + 1) { }
            }
            __threadfence();
        }
        __syncthreads();
    }
}

// ---------------------------------------------------------------------------
// Launch
// ---------------------------------------------------------------------------
extern "C" void kernel_launch(void* const* d_in, const int* in_sizes, int n_in,
                              void* d_out, int out_size) {
    const float* x  = (const float*)d_in[0];
    const float* h0 = (const float*)d_in[1];
    const float* Wx = (const float*)d_in[2];
    const float* Wh = (const float*)d_in[3];
    const float* b  = (const float*)d_in[4];
    float* out = (float*)d_out;

    cudaFuncSetAttribute(lstm_scan, cudaFuncAttributeMaxDynamicSharedMemorySize,
                         SMEM_BYTES);

    dim3 g1(G4 / 128, (Nn * T) / 128);
    gemm_xw<<<g1, 256>>>(x, Wx, b);
    lstm_init<<<(Nn * Hh + 255) / 256, 256>>>(h0);
    lstm_scan<<<NB, 256, SMEM_BYTES>>>(Wh, out);
}

// round 14
// speedup vs baseline: 1.7373x; 1.2460x over previous
#include <cuda_runtime.h>
#include <cuda_bf16.h>
#include <math.h>
#include <stdint.h>

#define Nn 64
#define T  512
#define Dd 512
#define Hh 512
#define G4 2048   // 4*H
#define NB 128    // persistent blocks
#define BPG 32    // blocks per batch group

// ---------------- scratch (static device arrays) ----------------
__device__ __align__(128) float g_xW[(size_t)Nn * T * G4];          // [t][n][4H]
__device__ __align__(128) __nv_bfloat16 g_hh[2][Nn * Hh];           // h hi plane [n][k]
__device__ __align__(128) __nv_bfloat16 g_hl[2][Nn * Hh];           // h lo plane [n][k]
__device__ __align__(128) __nv_bfloat16 g_xh[(size_t)Nn * T * Dd];  // x hi [m][k]
__device__ __align__(128) __nv_bfloat16 g_xl[(size_t)Nn * T * Dd];  // x lo [m][k]
__device__ __align__(128) __nv_bfloat16 g_wxh[G4 * Dd];             // Wx^T hi [n][k]
__device__ __align__(128) __nv_bfloat16 g_wxl[G4 * Dd];             // Wx^T lo [n][k]
__device__ int g_gcnt[4];
__device__ int g_flag[4];

// ---------------- helpers ----------------
static __device__ __forceinline__ uint32_t s2u(const void* p) {
    return (uint32_t)__cvta_generic_to_shared(p);
}
static __device__ __forceinline__ void cpasync16(uint32_t dst, const void* src) {
    asm volatile("cp.async.cg.shared.global [%0], [%1], 16;" :: "r"(dst), "l"(src));
}
static __device__ __forceinline__ void ldsm4(uint32_t* r, uint32_t addr) {
    asm volatile("ldmatrix.sync.aligned.m8n8.x4.shared.b16 {%0,%1,%2,%3}, [%4];"
                 : "=r"(r[0]), "=r"(r[1]), "=r"(r[2]), "=r"(r[3]) : "r"(addr));
}
static __device__ __forceinline__ void mma16816(float* d, const uint32_t* a,
                                                uint32_t b0, uint32_t b1) {
    asm volatile("mma.sync.aligned.m16n8k16.row.col.f32.bf16.bf16.f32 "
                 "{%0,%1,%2,%3},{%4,%5,%6,%7},{%8,%9},{%0,%1,%2,%3};"
                 : "+f"(d[0]), "+f"(d[1]), "+f"(d[2]), "+f"(d[3])
                 : "r"(a[0]), "r"(a[1]), "r"(a[2]), "r"(a[3]), "r"(b0), "r"(b1));
}

// ---------------------------------------------------------------------------
// Converts: x -> bf16 hi/lo planes [m][512]; Wx -> transposed hi/lo [n][512].
// ---------------------------------------------------------------------------
__global__ void convert_x(const float* __restrict__ x) {
    int i = blockIdx.x * blockDim.x + threadIdx.x;
    if (i < Nn * T * Dd) {
        float v = x[i];
        __nv_bfloat16 hi = __float2bfloat16(v);
        g_xh[i] = hi;
        g_xl[i] = __float2bfloat16(v - __bfloat162float(hi));
    }
}
__global__ void convert_wx(const float* __restrict__ Wx) {
    int i = blockIdx.x * blockDim.x + threadIdx.x;
    if (i < G4 * Dd) {
        int n = i >> 9;
        int k = i & 511;
        float v = Wx[(size_t)k * G4 + n];
        __nv_bfloat16 hi = __float2bfloat16(v);
        g_wxh[i] = hi;
        g_wxl[i] = __float2bfloat16(v - __bfloat162float(hi));
    }
}

// ---------------------------------------------------------------------------
// GEMM 1 via HMMA bf16 3-term split: g_xW[m -> (t,n)][2048] = x @ Wx + b.
// 128x128 tile, K staged 32/step (16 stages), double-buffered cp.async.
// 8 warps = 2m x 4n; warp tile 64m x 32n; D in registers (fp32).
// smem rows: 64B data at 80B pitch (8-row ldmatrix bank-distinct).
// ---------------------------------------------------------------------------
#define GSTAGE 40960   // bytes per buffer: A hi|lo 2*10240, B hi|lo 2*10240
#define GSMEM  (2 * GSTAGE)

__global__ __launch_bounds__(256) void gemm_xw_h(const float* __restrict__ b) {
    extern __shared__ char smem[];
    const uint32_t sbase = s2u(smem);

    const int tid  = threadIdx.x;
    const int lane = tid & 31;
    const int wid  = tid >> 5;
    const int wm   = wid >> 2;          // 0..1
    const int wn   = wid & 3;           // 0..3
    const int m0   = blockIdx.y * 128;
    const int n0   = blockIdx.x * 128;

    // ldmatrix lane addressing (proven scheme)
    const int tile = lane >> 3;
    const int tr   = lane & 7;
    const uint32_t arow  = (tile & 1) * 8 + tr;
    const uint32_t akoff = (tile >> 1) * 16;
    const uint32_t brow  = (tile >> 1) * 8 + tr;
    const uint32_t bkoff = (tile & 1) * 16;

    float d[4][4][4];
#pragma unroll
    for (int i = 0; i < 4; i++)
#pragma unroll
        for (int j = 0; j < 4; j++)
#pragma unroll
            for (int l = 0; l < 4; l++) d[i][j][l] = 0.f;

#define G_ISSUE(S)                                                            \
    {                                                                         \
        const int buf = (S) & 1;                                              \
        _Pragma("unroll")                                                     \
        for (int it = 0; it < 8; it++) {                                      \
            int id  = it * 256 + tid;                                         \
            int op  = id >> 10;                                               \
            int pl  = (id >> 9) & 1;                                          \
            int row = (id & 511) >> 2;                                        \
            int p   = id & 3;                                                 \
            uint32_t dst = sbase + (uint32_t)(buf * GSTAGE + op * 20480 +     \
                                              pl * 10240 + row * 80 + p * 16);\
            const char* src;                                                  \
            if (op == 0)                                                      \
                src = (const char*)(pl ? g_xl : g_xh) +                       \
                      (size_t)(m0 + row) * 1024 + (S) * 64 + p * 16;          \
            else                                                              \
                src = (const char*)(pl ? g_wxl : g_wxh) +                     \
                      (size_t)(n0 + row) * 1024 + (S) * 64 + p * 16;          \
            cpasync16(dst, src);                                              \
        }                                                                     \
        asm volatile("cp.async.commit_group;");                               \
    }

    G_ISSUE(0)

    for (int s = 0; s < 16; s++) {
        if (s + 1 < 16) {
            G_ISSUE(s + 1)
            asm volatile("cp.async.wait_group 1;");
        } else {
            asm volatile("cp.async.wait_group 0;");
        }
        __syncthreads();

        const int buf = s & 1;
        const uint32_t ah_base = sbase + buf * GSTAGE +
                                 (wm * 64 + arow) * 80 + akoff;
        const uint32_t al_base = ah_base + 10240;
        const uint32_t bh_base = sbase + buf * GSTAGE + 20480 +
                                 (wn * 32 + brow) * 80 + bkoff;
        const uint32_t bl_base = bh_base + 10240;

#pragma unroll
        for (int kc = 0; kc < 2; kc++) {
            const uint32_t ko = kc * 32;
            uint32_t bh0[4], bh1[4], bl0[4], bl1[4];
            ldsm4(bh0, bh_base + ko);
            ldsm4(bh1, bh_base + 16 * 80 + ko);
            ldsm4(bl0, bl_base + ko);
            ldsm4(bl1, bl_base + 16 * 80 + ko);
#pragma unroll
            for (int mi = 0; mi < 4; mi++) {
                uint32_t ah[4], al[4];
                ldsm4(ah, ah_base + mi * 16 * 80 + ko);
                ldsm4(al, al_base + mi * 16 * 80 + ko);
                mma16816(d[mi][0], ah, bh0[0], bh0[1]);
                mma16816(d[mi][1], ah, bh0[2], bh0[3]);
                mma16816(d[mi][2], ah, bh1[0], bh1[1]);
                mma16816(d[mi][3], ah, bh1[2], bh1[3]);
                mma16816(d[mi][0], ah, bl0[0], bl0[1]);
                mma16816(d[mi][1], ah, bl0[2], bl0[3]);
                mma16816(d[mi][2], ah, bl1[0], bl1[1]);
                mma16816(d[mi][3], ah, bl1[2], bl1[3]);
                mma16816(d[mi][0], al, bh0[0], bh0[1]);
                mma16816(d[mi][1], al, bh0[2], bh0[3]);
                mma16816(d[mi][2], al, bh1[0], bh1[1]);
                mma16816(d[mi][3], al, bh1[2], bh1[3]);
            }
        }
        __syncthreads();
    }
#undef G_ISSUE

    // epilogue: bias + relayout write. Thread owns rows (lane>>2)+{0,8},
    // cols 2*(lane&3)+{0,1} within each m16n8 tile.
    const int cbase0 = n0 + wn * 32 + (lane & 3) * 2;
#pragma unroll
    for (int ni = 0; ni < 4; ni++) {
        const int cb = cbase0 + ni * 8;
        float2 bb = *(const float2*)&b[cb];
#pragma unroll
        for (int mi = 0; mi < 4; mi++) {
#pragma unroll
            for (int half = 0; half < 2; half++) {
                int m  = m0 + wm * 64 + mi * 16 + (lane >> 2) + half * 8;
                int tt = m & (T - 1);
                int nn = m >> 9;
                size_t row = ((size_t)tt * Nn + nn) * G4 + cb;
                *(float2*)&g_xW[row] =
                    make_float2(d[mi][ni][half * 2 + 0] + bb.x,
                                d[mi][ni][half * 2 + 1] + bb.y);
            }
        }
    }
}

// ---------------------------------------------------------------------------
// Init: h0 -> bf16 hi/lo planes [n][k]; reset counters/flags.
// ---------------------------------------------------------------------------
__global__ void lstm_init(const float* __restrict__ h0) {
    int i = blockIdx.x * blockDim.x + threadIdx.x;
    if (i < Nn * Hh) {
        float v = h0[i];
        __nv_bfloat16 hi = __float2bfloat16(v);
        g_hh[0][i] = hi;
        g_hl[0][i] = __float2bfloat16(v - __bfloat162float(hi));
    }
    if (i < 4) { g_gcnt[i] = 0; g_flag[i] = 0; }
}

// smem byte layout for scan (pitch 1040 B = 520 halves)
#define OFF_WHI  0
#define OFF_WLO  66560
#define OFF_HH   133120
#define OFF_HL   149760
#define OFF_SACC 166400
#define SMEM_BYTES (OFF_SACC + 4 * 64 * 20 * 4)

// ---------------------------------------------------------------------------
// Persistent HMMA scan (r13, best measured — unchanged).
// ---------------------------------------------------------------------------
__global__ __launch_bounds__(256) void lstm_scan(const float* __restrict__ Wh,
                                                 float* __restrict__ out) {
    extern __shared__ char smem[];
    __nv_bfloat16* whi = (__nv_bfloat16*)(smem + OFF_WHI);
    __nv_bfloat16* wlo = (__nv_bfloat16*)(smem + OFF_WLO);
    float* sacc = (float*)(smem + OFF_SACC);   // [4][64][20]

    const int tid  = threadIdx.x;
    const int lane = tid & 31;
    const int wid  = tid >> 5;
    const int hb   = blockIdx.x;
    const int ng   = hb >> 5;
    const int hg   = hb & 31;
    const int mw   = wid & 1;
    const int kw   = wid >> 1;
    const int n_e  = tid & 15;
    const int u_e  = tid >> 4;

    for (int idx = tid; idx < 64 * 512; idx += 256) {
        int c = idx & 63;
        int k = idx >> 6;
        int u = c >> 2;
        int g = c & 3;
        float w = Wh[(size_t)k * G4 + g * Hh + hg * 16 + u];
        __nv_bfloat16 hi = __float2bfloat16(w);
        whi[c * 520 + k] = hi;
        wlo[c * 520 + k] = __float2bfloat16(w - __bfloat162float(hi));
    }

    const int tile = lane >> 3;
    const int tr   = lane & 7;
    const uint32_t a_row16 = (tile & 1) * 8 + tr;
    const uint32_t a_koff  = (tile >> 1) * 16;
    const uint32_t b_c     = (tile >> 1) * 8 + tr;
    const uint32_t b_koff  = (tile & 1) * 16;
    const uint32_t aHi0 = s2u(whi) + (mw * 32 + a_row16) * 1040 + a_koff;
    const uint32_t aHi1 = aHi0 + 16 * 1040;
    const uint32_t aLo0 = s2u(wlo) + (mw * 32 + a_row16) * 1040 + a_koff;
    const uint32_t aLo1 = aLo0 + 16 * 1040;
    const uint32_t bHH  = s2u(smem + OFF_HH) + b_c * 1040 + b_koff;
    const uint32_t bHL  = s2u(smem + OFF_HL) + b_c * 1040 + b_koff;

    float c_reg = 0.f;

    for (int t = 0; t < T; t++) {
        const int cur = t & 1;
        const __nv_bfloat16* ghh = g_hh[cur];
        const __nv_bfloat16* ghl = g_hl[cur];

        const int gn = ng * 16 + n_e;
        const int gk = hg * 16 + u_e;
        const float* xwp = g_xW + ((size_t)t * Nn + gn) * G4 + hg * 16 + u_e;
        float xw0 = xwp[0 * Hh];
        float xw1 = xwp[1 * Hh];
        float xw2 = xwp[2 * Hh];
        float xw3 = xwp[3 * Hh];

#pragma unroll
        for (int c = 0; c < 4; c++) {
#pragma unroll
            for (int it = 0; it < 2; it++) {
                int id = it * 256 + tid;
                int p  = id >> 8;
                int n  = (id >> 4) & 15;
                int q  = c * 16 + (id & 15);
                uint32_t dst = s2u(smem + (p ? OFF_HL : OFF_HH)) +
                               (uint32_t)n * 1040u + (uint32_t)q * 16u;
                const char* src = (const char*)(p ? ghl : ghh) +
                                  (size_t)(ng * 16 + n) * 1024 + (size_t)q * 16;
                cpasync16(dst, src);
            }
            asm volatile("cp.async.commit_group;");
        }

        float d00[4] = {0, 0, 0, 0}, d01[4] = {0, 0, 0, 0};
        float d10[4] = {0, 0, 0, 0}, d11[4] = {0, 0, 0, 0};

#define MMA_PHASE(C, WG)                                                      \
        {                                                                     \
            asm volatile("cp.async.wait_group %0;" :: "n"(WG));               \
            __syncthreads();                                                  \
            _Pragma("unroll")                                                 \
            for (int kc2 = 0; kc2 < 2; kc2++) {                               \
                const uint32_t off = (uint32_t)(((C) * 8 + kw * 2 + kc2) * 32); \
                uint32_t ah0[4], ah1[4], al0[4], al1[4], bh[4], bl[4];        \
                ldsm4(ah0, aHi0 + off);                                       \
                ldsm4(ah1, aHi1 + off);                                       \
                ldsm4(bh,  bHH  + off);                                       \
                ldsm4(bl,  bHL  + off);                                       \
                ldsm4(al0, aLo0 + off);                                       \
                ldsm4(al1, aLo1 + off);                                       \
                mma16816(d00, ah0, bh[0], bh[1]);                             \
                mma16816(d01, ah0, bh[2], bh[3]);                             \
                mma16816(d10, ah1, bh[0], bh[1]);                             \
                mma16816(d11, ah1, bh[2], bh[3]);                             \
                mma16816(d00, ah0, bl[0], bl[1]);                             \
                mma16816(d01, ah0, bl[2], bl[3]);                             \
                mma16816(d10, ah1, bl[0], bl[1]);                             \
                mma16816(d11, ah1, bl[2], bl[3]);                             \
                mma16816(d00, al0, bh[0], bh[1]);                             \
                mma16816(d01, al0, bh[2], bh[3]);                             \
                mma16816(d10, al1, bh[0], bh[1]);                             \
                mma16816(d11, al1, bh[2], bh[3]);                             \
            }                                                                 \
        }
        MMA_PHASE(0, 3)
        MMA_PHASE(1, 2)
        MMA_PHASE(2, 1)
        MMA_PHASE(3, 0)
#undef MMA_PHASE

        {
            const int crow = mw * 32 + (lane >> 2);
            const int ncol = (lane & 3) * 2;
            float* sa = sacc + kw * 64 * 20;
            *(float2*)&sa[(crow)      * 20 + ncol]     = make_float2(d00[0], d00[1]);
            *(float2*)&sa[(crow + 8)  * 20 + ncol]     = make_float2(d00[2], d00[3]);
            *(float2*)&sa[(crow)      * 20 + ncol + 8] = make_float2(d01[0], d01[1]);
            *(float2*)&sa[(crow + 8)  * 20 + ncol + 8] = make_float2(d01[2], d01[3]);
            *(float2*)&sa[(crow + 16) * 20 + ncol]     = make_float2(d10[0], d10[1]);
            *(float2*)&sa[(crow + 24) * 20 + ncol]     = make_float2(d10[2], d10[3]);
            *(float2*)&sa[(crow + 16) * 20 + ncol + 8] = make_float2(d11[0], d11[1]);
            *(float2*)&sa[(crow + 24) * 20 + ncol + 8] = make_float2(d11[2], d11[3]);
        }
        __syncthreads();

        {
            float ag[4];
#pragma unroll
            for (int g = 0; g < 4; g++) {
                int c = u_e * 4 + g;
                ag[g] = sacc[(0 * 64 + c) * 20 + n_e]
                      + sacc[(1 * 64 + c) * 20 + n_e]
                      + sacc[(2 * 64 + c) * 20 + n_e]
                      + sacc[(3 * 64 + c) * 20 + n_e];
            }
            ag[0] += xw0; ag[1] += xw1; ag[2] += xw2; ag[3] += xw3;

            float iv = 1.f / (1.f + expf(-ag[0]));
            float fv = 1.f / (1.f + expf(-ag[1]));
            float ov = 1.f / (1.f + expf(-ag[2]));
            float gv = tanhf(ag[3]);

            c_reg = fv * c_reg + iv * gv;
            float hn = ov * tanhf(c_reg);

            __nv_bfloat16 hi = __float2bfloat16(hn);
            g_hh[cur ^ 1][gn * Hh + gk] = hi;
            g_hl[cur ^ 1][gn * Hh + gk] =
                __float2bfloat16(hn - __bfloat162float(hi));
            out[((size_t)gn * T + t) * Hh + gk] = hn;
        }
        __syncthreads();

        if (tid == 0) {
            __threadfence();
            int v = atomicAdd(&g_gcnt[ng], 1);
            if (v == BPG - 1) {
                g_gcnt[ng] = 0;
                __threadfence();
                *(volatile int*)&g_flag[ng] = t + 1;
            } else {
                while (*(volatile int*)&g_flag[ng] < t + 1) { }
            }
            __threadfence();
        }
        __syncthreads();
    }
}

// ---------------------------------------------------------------------------
// Launch
// ---------------------------------------------------------------------------
extern "C" void kernel_launch(void* const* d_in, const int* in_sizes, int n_in,
                              void* d_out, int out_size) {
    const float* x  = (const float*)d_in[0];
    const float* h0 = (const float*)d_in[1];
    const float* Wx = (const float*)d_in[2];
    const float* Wh = (const float*)d_in[3];
    const float* b  = (const float*)d_in[4];
    float* out = (float*)d_out;

    cudaFuncSetAttribute(lstm_scan, cudaFuncAttributeMaxDynamicSharedMemorySize,
                         SMEM_BYTES);
    cudaFuncSetAttribute(gemm_xw_h, cudaFuncAttributeMaxDynamicSharedMemorySize,
                         GSMEM);

    convert_x<<<(Nn * T * Dd + 255) / 256, 256>>>(x);
    convert_wx<<<(G4 * Dd + 255) / 256, 256>>>(Wx);

    dim3 g1(G4 / 128, (Nn * T) / 128);   // (16, 256)
    gemm_xw_h<<<g1, 256, GSMEM>>>(b);

    lstm_init<<<(Nn * Hh + 255) / 256, 256>>>(h0);
    lstm_scan<<<NB, 256, SMEM_BYTES>>>(Wh, out);
}